// round 1
// baseline (speedup 1.0000x reference)
#include <cuda_runtime.h>
#include <cuda_bf16.h>
#include <stdint.h>

// Problem constants (fixed by setup_inputs): N=4096 rows, D=512
#define NROW 4096
#define DDIM 512

// Fused gram+KL tiling
#define BM 64
#define BN 64
#define BK 32
#define NSPLIT 4
#define JRANGE (NROW / NSPLIT)   // 1024 j per CTA
#define NJT (JRANGE / BN)        // 16 j-tiles per CTA
#define APITCH 40                // bf16 pitch (32 + 8) -> 80B rows, 16B aligned for ldmatrix
#define CPITCH 65                // fp32 staging pitch

// ---------------- device scratch (allocation-free contract) ----------------
__device__ __align__(16) __nv_bfloat16 g_Xn[NROW * DDIM];
__device__ __align__(16) __nv_bfloat16 g_Yn[NROW * DDIM];
__device__ float g_part[NROW * NSPLIT * 5];   // m_a, l_a, s, m_b, l_b
__device__ float g_kl[NROW];

// ---------------- PTX helpers ----------------
__device__ __forceinline__ void ldm_x4(uint32_t &r0, uint32_t &r1, uint32_t &r2,
                                       uint32_t &r3, uint32_t addr) {
  asm volatile("ldmatrix.sync.aligned.m8n8.x4.shared.b16 {%0,%1,%2,%3}, [%4];\n"
               : "=r"(r0), "=r"(r1), "=r"(r2), "=r"(r3)
               : "r"(addr));
}

__device__ __forceinline__ void mma_bf16(float *c, const uint32_t *a,
                                         const uint32_t *b) {
  asm volatile(
      "mma.sync.aligned.m16n8k16.row.col.f32.bf16.bf16.f32 "
      "{%0,%1,%2,%3}, {%4,%5,%6,%7}, {%8,%9}, {%0,%1,%2,%3};\n"
      : "+f"(c[0]), "+f"(c[1]), "+f"(c[2]), "+f"(c[3])
      : "r"(a[0]), "r"(a[1]), "r"(a[2]), "r"(a[3]), "r"(b[0]), "r"(b[1]));
}

// ---------------- 1) row-normalize fp32 -> bf16 ----------------
// grid (NROW, 2), 128 threads. blockIdx.y selects X or Y.
__global__ void normalize_kernel(const float *__restrict__ X,
                                 const float *__restrict__ Y) {
  const int row = blockIdx.x;
  const float *src = blockIdx.y ? Y : X;
  __nv_bfloat16 *dst = blockIdx.y ? g_Yn : g_Xn;
  const int tid = threadIdx.x;  // 128 threads, one float4 each (512 floats/row)

  float4 v = reinterpret_cast<const float4 *>(src)[row * (DDIM / 4) + tid];
  float ss = v.x * v.x + v.y * v.y + v.z * v.z + v.w * v.w;
#pragma unroll
  for (int o = 16; o > 0; o >>= 1) ss += __shfl_xor_sync(0xffffffffu, ss, o);
  __shared__ float wsum[4];
  if ((tid & 31) == 0) wsum[tid >> 5] = ss;
  __syncthreads();
  const float tot = wsum[0] + wsum[1] + wsum[2] + wsum[3];
  const float inv = 1.0f / fmaxf(sqrtf(tot), 1e-8f);

  __nv_bfloat162 p0 = __floats2bfloat162_rn(v.x * inv, v.y * inv);
  __nv_bfloat162 p1 = __floats2bfloat162_rn(v.z * inv, v.w * inv);
  uint2 packed;
  packed.x = *reinterpret_cast<uint32_t *>(&p0);
  packed.y = *reinterpret_cast<uint32_t *>(&p1);
  reinterpret_cast<uint2 *>(dst)[row * (DDIM / 4) + tid] = packed;
}

// ---------------- 2) fused gram + online softmax-KL ----------------
struct GemmSmem {
  __nv_bfloat16 xi[BM * APITCH];
  __nv_bfloat16 xj[BN * APITCH];
  __nv_bfloat16 yi[BM * APITCH];
  __nv_bfloat16 yj[BN * APITCH];
};
struct StageSmem {
  float a[BM * CPITCH];
  float b[BM * CPITCH];
};
union KSmem {
  GemmSmem g;
  StageSmem s;
};

__global__ void __launch_bounds__(256, 2) gram_kl_kernel() {
  __shared__ __align__(16) KSmem sm;

  const int tid = threadIdx.x;
  const int lane = tid & 31;
  const int wid = tid >> 5;
  const int wm = wid & 3;   // warp row group: rows wm*16
  const int wn = wid >> 2;  // warp col group: cols wn*32
  const int i0 = blockIdx.x * BM;
  const int split = blockIdx.y;
  const int j0 = split * JRANGE;

  // global->smem staging map: 64 rows x 32 bf16 (= 4 x 16B chunks per row)
  const int lrow = tid >> 2;
  const int lch = tid & 3;

  // ldmatrix source coordinates (within tile)
  const int a_row = wm * 16 + (lane & 15);
  const int a_col = (lane >> 4) * 8;
  const int b_rowoff = ((lane >> 4) << 3) + (lane & 7);
  const int b_col = ((lane >> 3) & 1) * 8;

  const uint32_t xi_base = (uint32_t)__cvta_generic_to_shared(sm.g.xi);
  const uint32_t xj_base = (uint32_t)__cvta_generic_to_shared(sm.g.xj);
  const uint32_t yi_base = (uint32_t)__cvta_generic_to_shared(sm.g.yi);
  const uint32_t yj_base = (uint32_t)__cvta_generic_to_shared(sm.g.yj);

  // online softmax/KL state (kept redundantly by each 4-lane quad of a row)
  const int srow = tid >> 2;
  const int q = tid & 3;
  float m_a = -1e30f, l_a = 0.f, s_ab = 0.f, m_b = -1e30f, l_b = 0.f;

  for (int jt = 0; jt < NJT; jt++) {
    const int j = j0 + jt * BN;
    float accA[4][4], accB[4][4];
#pragma unroll
    for (int n = 0; n < 4; n++)
#pragma unroll
      for (int r = 0; r < 4; r++) {
        accA[n][r] = 0.f;
        accB[n][r] = 0.f;
      }

    for (int k0 = 0; k0 < DDIM; k0 += BK) {
      __syncthreads();  // protect smem from prior stage readers / softmax phase
      const uint4 vxi = *reinterpret_cast<const uint4 *>(
          &g_Xn[(i0 + lrow) * DDIM + k0 + lch * 8]);
      const uint4 vxj = *reinterpret_cast<const uint4 *>(
          &g_Xn[(j + lrow) * DDIM + k0 + lch * 8]);
      const uint4 vyi = *reinterpret_cast<const uint4 *>(
          &g_Yn[(i0 + lrow) * DDIM + k0 + lch * 8]);
      const uint4 vyj = *reinterpret_cast<const uint4 *>(
          &g_Yn[(j + lrow) * DDIM + k0 + lch * 8]);
      *reinterpret_cast<uint4 *>(&sm.g.xi[lrow * APITCH + lch * 8]) = vxi;
      *reinterpret_cast<uint4 *>(&sm.g.xj[lrow * APITCH + lch * 8]) = vxj;
      *reinterpret_cast<uint4 *>(&sm.g.yi[lrow * APITCH + lch * 8]) = vyi;
      *reinterpret_cast<uint4 *>(&sm.g.yj[lrow * APITCH + lch * 8]) = vyj;
      __syncthreads();

#pragma unroll
      for (int kk = 0; kk < BK; kk += 16) {
        uint32_t ax[4], ay[4], bx[2][4], by[2][4];
        ldm_x4(ax[0], ax[1], ax[2], ax[3],
               xi_base + 2u * (a_row * APITCH + kk + a_col));
        ldm_x4(ay[0], ay[1], ay[2], ay[3],
               yi_base + 2u * (a_row * APITCH + kk + a_col));
#pragma unroll
        for (int p = 0; p < 2; p++) {
          ldm_x4(bx[p][0], bx[p][1], bx[p][2], bx[p][3],
                 xj_base + 2u * ((wn * 32 + p * 16 + b_rowoff) * APITCH + kk + b_col));
          ldm_x4(by[p][0], by[p][1], by[p][2], by[p][3],
                 yj_base + 2u * ((wn * 32 + p * 16 + b_rowoff) * APITCH + kk + b_col));
        }
#pragma unroll
        for (int p = 0; p < 2; p++) {
          mma_bf16(&accA[2 * p + 0][0], ax, &bx[p][0]);
          mma_bf16(&accA[2 * p + 1][0], ax, &bx[p][2]);
          mma_bf16(&accB[2 * p + 0][0], ay, &by[p][0]);
          mma_bf16(&accB[2 * p + 1][0], ay, &by[p][2]);
        }
      }
    }

    __syncthreads();  // all warps done reading gemm smem before staging overwrite
    // stage fp32 score tiles: A = Xi.Xj^T, B = Yi.Yj^T
#pragma unroll
    for (int n = 0; n < 4; n++) {
      const int crow = wm * 16 + (lane >> 2);
      const int ccol = wn * 32 + n * 8 + (lane & 3) * 2;
      sm.s.a[crow * CPITCH + ccol] = accA[n][0];
      sm.s.a[crow * CPITCH + ccol + 1] = accA[n][1];
      sm.s.a[(crow + 8) * CPITCH + ccol] = accA[n][2];
      sm.s.a[(crow + 8) * CPITCH + ccol + 1] = accA[n][3];
      sm.s.b[crow * CPITCH + ccol] = accB[n][0];
      sm.s.b[crow * CPITCH + ccol + 1] = accB[n][1];
      sm.s.b[(crow + 8) * CPITCH + ccol] = accB[n][2];
      sm.s.b[(crow + 8) * CPITCH + ccol + 1] = accB[n][3];
    }
    __syncthreads();

    // online update. logits: a = -simX, b = -simY (constant shifts cancel in KL)
    float ta_max = -1e30f, tb_max = -1e30f;
#pragma unroll
    for (int c = q; c < BN; c += 4) {
      ta_max = fmaxf(ta_max, -sm.s.a[srow * CPITCH + c]);
      tb_max = fmaxf(tb_max, -sm.s.b[srow * CPITCH + c]);
    }
    ta_max = fmaxf(ta_max, __shfl_xor_sync(0xffffffffu, ta_max, 1));
    ta_max = fmaxf(ta_max, __shfl_xor_sync(0xffffffffu, ta_max, 2));
    tb_max = fmaxf(tb_max, __shfl_xor_sync(0xffffffffu, tb_max, 1));
    tb_max = fmaxf(tb_max, __shfl_xor_sync(0xffffffffu, tb_max, 2));

    const float nm_a = fmaxf(m_a, ta_max);
    const float nm_b = fmaxf(m_b, tb_max);
    float la_t = 0.f, s_t = 0.f, lb_t = 0.f;
#pragma unroll
    for (int c = q; c < BN; c += 4) {
      const float av = -sm.s.a[srow * CPITCH + c];
      const float bv = -sm.s.b[srow * CPITCH + c];
      const float e = __expf(av - nm_a);
      la_t += e;
      s_t += e * (av - bv);
      lb_t += __expf(bv - nm_b);
    }
    la_t += __shfl_xor_sync(0xffffffffu, la_t, 1);
    la_t += __shfl_xor_sync(0xffffffffu, la_t, 2);
    s_t += __shfl_xor_sync(0xffffffffu, s_t, 1);
    s_t += __shfl_xor_sync(0xffffffffu, s_t, 2);
    lb_t += __shfl_xor_sync(0xffffffffu, lb_t, 1);
    lb_t += __shfl_xor_sync(0xffffffffu, lb_t, 2);

    const float sc_a = __expf(m_a - nm_a);
    const float sc_b = __expf(m_b - nm_b);
    l_a = l_a * sc_a + la_t;
    s_ab = s_ab * sc_a + s_t;
    l_b = l_b * sc_b + lb_t;
    m_a = nm_a;
    m_b = nm_b;
  }

  if (q == 0) {
    const int base = ((i0 + srow) * NSPLIT + split) * 5;
    g_part[base + 0] = m_a;
    g_part[base + 1] = l_a;
    g_part[base + 2] = s_ab;
    g_part[base + 3] = m_b;
    g_part[base + 4] = l_b;
  }
}

// ---------------- 3) merge j-splits per row ----------------
__global__ void merge_kernel() {
  const int row = blockIdx.x * blockDim.x + threadIdx.x;
  if (row >= NROW) return;
  const float *p = &g_part[row * NSPLIT * 5];
  float Ma = -1e30f, Mb = -1e30f;
#pragma unroll
  for (int k = 0; k < NSPLIT; k++) {
    Ma = fmaxf(Ma, p[k * 5 + 0]);
    Mb = fmaxf(Mb, p[k * 5 + 3]);
  }
  float L = 0.f, S = 0.f, Lb = 0.f;
#pragma unroll
  for (int k = 0; k < NSPLIT; k++) {
    const float w = __expf(p[k * 5 + 0] - Ma);
    L += p[k * 5 + 1] * w;
    S += p[k * 5 + 2] * w;
    Lb += p[k * 5 + 4] * __expf(p[k * 5 + 3] - Mb);
  }
  const float lse_a = Ma + logf(L);
  const float lse_b = Mb + logf(Lb);
  g_kl[row] = S / L - lse_a + lse_b;
}

// ---------------- 4) deterministic mean ----------------
__global__ void reduce_kernel(float *__restrict__ out) {
  __shared__ float red[256];
  const int tid = threadIdx.x;
  float s = 0.f;
  for (int i = tid; i < NROW; i += 256) s += g_kl[i];
  red[tid] = s;
  __syncthreads();
#pragma unroll
  for (int o = 128; o > 0; o >>= 1) {
    if (tid < o) red[tid] += red[tid + o];
    __syncthreads();
  }
  if (tid == 0) out[0] = red[0] / (float)NROW;
}

// ---------------- launch ----------------
extern "C" void kernel_launch(void *const *d_in, const int *in_sizes, int n_in,
                              void *d_out, int out_size) {
  const float *X = (const float *)d_in[0];  // cosine_distance_latent (target)
  const float *Y = (const float *)d_in[1];  // mse_latent (predicted)
  float *out = (float *)d_out;

  normalize_kernel<<<dim3(NROW, 2), 128>>>(X, Y);
  gram_kl_kernel<<<dim3(NROW / BM, NSPLIT), 256>>>();
  merge_kernel<<<NROW / 256, 256>>>();
  reduce_kernel<<<1, 256>>>(out);
}

// round 2
// speedup vs baseline: 1.5079x; 1.5079x over previous
#include <cuda_runtime.h>
#include <cuda_bf16.h>
#include <stdint.h>

// Problem constants (fixed by setup_inputs): N=4096 rows, D=512
#define NROW 4096
#define DDIM 512

// Fused gram+KL tiling
#define BM 64
#define BN 64
#define BK 64
#define NSPLIT 2
#define JRANGE (NROW / NSPLIT)     // 2048 j per CTA
#define NJT (JRANGE / BN)          // 32 j-tiles per CTA
#define KSTAGES (DDIM / BK)        // 8 k-stages per j-tile
#define S_STAGES (NJT * KSTAGES)   // 256 flat stages

#define XI_PITCH 520               // bf16 pitch for persistent i-tiles (1040B rows)
#define ST_PITCH 72                // bf16 pitch for streaming j-stage tiles (144B rows)

// dynamic smem layout (bytes)
#define XI_OFF 0
#define YI_OFF (BM * XI_PITCH * 2)                     // 66560
#define STAGE_OFF (2 * BM * XI_PITCH * 2)              // 133120
#define STAGE_TILE (BN * ST_PITCH * 2)                 // 9216 (xj), yj at +9216
#define STAGE_BYTES (2 * STAGE_TILE)                   // 18432 per stage
#define SMEM_TOTAL (STAGE_OFF + 3 * STAGE_BYTES)       // 188416

// ---------------- device scratch (allocation-free contract) ----------------
__device__ __align__(16) __nv_bfloat16 g_Xn[NROW * DDIM];
__device__ __align__(16) __nv_bfloat16 g_Yn[NROW * DDIM];
// per row: 4 partial slots (split*2 + wn) x {l_a, s, l_b}
__device__ float g_part[NROW * 12];

// ---------------- PTX helpers ----------------
__device__ __forceinline__ void ldm_x4(uint32_t &r0, uint32_t &r1, uint32_t &r2,
                                       uint32_t &r3, uint32_t addr) {
  asm volatile("ldmatrix.sync.aligned.m8n8.x4.shared.b16 {%0,%1,%2,%3}, [%4];\n"
               : "=r"(r0), "=r"(r1), "=r"(r2), "=r"(r3)
               : "r"(addr));
}

__device__ __forceinline__ void mma_bf16(float *c, const uint32_t *a,
                                         const uint32_t *b) {
  asm volatile(
      "mma.sync.aligned.m16n8k16.row.col.f32.bf16.bf16.f32 "
      "{%0,%1,%2,%3}, {%4,%5,%6,%7}, {%8,%9}, {%0,%1,%2,%3};\n"
      : "+f"(c[0]), "+f"(c[1]), "+f"(c[2]), "+f"(c[3])
      : "r"(a[0]), "r"(a[1]), "r"(a[2]), "r"(a[3]), "r"(b[0]), "r"(b[1]));
}

__device__ __forceinline__ void cp16(uint32_t saddr, const void *gaddr) {
  asm volatile("cp.async.cg.shared.global [%0], [%1], 16;\n" ::"r"(saddr),
               "l"(gaddr));
}
__device__ __forceinline__ void cp_commit() {
  asm volatile("cp.async.commit_group;\n");
}
template <int N> __device__ __forceinline__ void cp_wait() {
  asm volatile("cp.async.wait_group %0;\n" ::"n"(N));
}

// ---------------- 1) row-normalize fp32 -> bf16 ----------------
__global__ void normalize_kernel(const float *__restrict__ X,
                                 const float *__restrict__ Y) {
  const int row = blockIdx.x;
  const float *src = blockIdx.y ? Y : X;
  __nv_bfloat16 *dst = blockIdx.y ? g_Yn : g_Xn;
  const int tid = threadIdx.x;  // 128 threads, one float4 each

  float4 v = reinterpret_cast<const float4 *>(src)[row * (DDIM / 4) + tid];
  float ss = v.x * v.x + v.y * v.y + v.z * v.z + v.w * v.w;
#pragma unroll
  for (int o = 16; o > 0; o >>= 1) ss += __shfl_xor_sync(0xffffffffu, ss, o);
  __shared__ float wsum[4];
  if ((tid & 31) == 0) wsum[tid >> 5] = ss;
  __syncthreads();
  const float tot = wsum[0] + wsum[1] + wsum[2] + wsum[3];
  const float inv = 1.0f / fmaxf(sqrtf(tot), 1e-8f);

  __nv_bfloat162 p0 = __floats2bfloat162_rn(v.x * inv, v.y * inv);
  __nv_bfloat162 p1 = __floats2bfloat162_rn(v.z * inv, v.w * inv);
  uint2 packed;
  packed.x = *reinterpret_cast<uint32_t *>(&p0);
  packed.y = *reinterpret_cast<uint32_t *>(&p1);
  reinterpret_cast<uint2 *>(dst)[row * (DDIM / 4) + tid] = packed;
}

// ---------------- 2) fused gram + fixed-shift softmax-KL ----------------
extern __shared__ __align__(16) unsigned char smem_raw[];

__global__ void __launch_bounds__(256, 1) gram_kl_kernel() {
  const int tid = threadIdx.x;
  const int lane = tid & 31;
  const int wid = tid >> 5;
  const int wm = wid & 3;   // warp row group: rows wm*16
  const int wn = wid >> 2;  // warp col group: cols wn*32
  const int i0 = blockIdx.x * BM;
  const int split = blockIdx.y;
  const int j0 = split * JRANGE;

  const uint32_t smem_base = (uint32_t)__cvta_generic_to_shared(smem_raw);
  const uint32_t xi_base = smem_base + XI_OFF;
  const uint32_t yi_base = smem_base + YI_OFF;

  // ------- persistent Xi/Yi tiles (full D) via cp.async, group 0 -------
  {
    const int row = tid >> 2;
#pragma unroll
    for (int c = (tid & 3); c < DDIM / 8; c += 4) {  // 16B chunks (8 bf16)
      cp16(xi_base + row * (XI_PITCH * 2) + c * 16,
           &g_Xn[(i0 + row) * DDIM + c * 8]);
      cp16(yi_base + row * (XI_PITCH * 2) + c * 16,
           &g_Yn[(i0 + row) * DDIM + c * 8]);
    }
    cp_commit();
  }

  // stage loader lambda-equivalent
  const int lrow = tid >> 2;
  const int lch = tid & 3;
  auto load_stage = [&](int s) {
    const int jt = s >> 3;
    const int k0 = (s & 7) * BK;
    const int j = j0 + jt * BN;
    const uint32_t st = smem_base + STAGE_OFF + (s % 3) * STAGE_BYTES;
#pragma unroll
    for (int c = lch; c < BK / 8; c += 4) {
      cp16(st + lrow * (ST_PITCH * 2) + c * 16,
           &g_Xn[(j + lrow) * DDIM + k0 + c * 8]);
      cp16(st + STAGE_TILE + lrow * (ST_PITCH * 2) + c * 16,
           &g_Yn[(j + lrow) * DDIM + k0 + c * 8]);
    }
    cp_commit();
  };

  // prefetch stages 0..2 (groups 1..3)
  load_stage(0);
  load_stage(1);
  load_stage(2);

  // ldmatrix coordinates (proven layout from R1)
  const int a_row = wm * 16 + (lane & 15);
  const int a_col = (lane >> 4) * 8;
  const int b_rowoff = ((lane >> 4) << 3) + (lane & 7);
  const int b_col = ((lane >> 3) & 1) * 8;

  float accA[4][4], accB[4][4];
#pragma unroll
  for (int n = 0; n < 4; n++)
#pragma unroll
    for (int r = 0; r < 4; r++) {
      accA[n][r] = 0.f;
      accB[n][r] = 0.f;
    }
  // per-thread running KL partial sums for the 2 fragment rows
  float la0 = 0.f, la1 = 0.f, s0 = 0.f, s1 = 0.f, lb0 = 0.f, lb1 = 0.f;

  for (int s = 0; s < S_STAGES; s++) {
    cp_wait<2>();  // stage s (and Xi/Yi on s==0) landed
    __syncthreads();

    const uint32_t xj_b = smem_base + STAGE_OFF + (s % 3) * STAGE_BYTES;
    const uint32_t yj_b = xj_b + STAGE_TILE;
    const int kabs = (s & 7) * BK;

#pragma unroll
    for (int kk = 0; kk < BK; kk += 16) {
      uint32_t ax[4], ay[4], bx[2][4], by[2][4];
      ldm_x4(ax[0], ax[1], ax[2], ax[3],
             xi_base + 2u * (a_row * XI_PITCH + kabs + kk + a_col));
      ldm_x4(ay[0], ay[1], ay[2], ay[3],
             yi_base + 2u * (a_row * XI_PITCH + kabs + kk + a_col));
#pragma unroll
      for (int p = 0; p < 2; p++) {
        ldm_x4(bx[p][0], bx[p][1], bx[p][2], bx[p][3],
               xj_b + 2u * ((wn * 32 + p * 16 + b_rowoff) * ST_PITCH + kk + b_col));
        ldm_x4(by[p][0], by[p][1], by[p][2], by[p][3],
               yj_b + 2u * ((wn * 32 + p * 16 + b_rowoff) * ST_PITCH + kk + b_col));
      }
#pragma unroll
      for (int p = 0; p < 2; p++) {
        mma_bf16(&accA[2 * p + 0][0], ax, &bx[p][0]);
        mma_bf16(&accA[2 * p + 1][0], ax, &bx[p][2]);
        mma_bf16(&accB[2 * p + 0][0], ay, &by[p][0]);
        mma_bf16(&accB[2 * p + 1][0], ay, &by[p][2]);
      }
    }

    __syncthreads();  // all warps done reading buf s%3 before it is refilled
    if (s + 3 < S_STAGES) load_stage(s + 3);

    if ((s & 7) == 7) {
      // register-only epilogue: logits a=-A, b=-B are in [-1,1]; fixed shift 0.
      // l_a += e^a ; s += e^a*(a-b) = e^{-A}*(B-A) ; l_b += e^b
#pragma unroll
      for (int n = 0; n < 4; n++) {
        {
          const float A0 = accA[n][0], B0 = accB[n][0];
          const float A1 = accA[n][1], B1 = accB[n][1];
          const float e0 = __expf(-A0), e1 = __expf(-A1);
          la0 += e0 + e1;
          s0 += e0 * (B0 - A0) + e1 * (B1 - A1);
          lb0 += __expf(-B0) + __expf(-B1);
        }
        {
          const float A0 = accA[n][2], B0 = accB[n][2];
          const float A1 = accA[n][3], B1 = accB[n][3];
          const float e0 = __expf(-A0), e1 = __expf(-A1);
          la1 += e0 + e1;
          s1 += e0 * (B0 - A0) + e1 * (B1 - A1);
          lb1 += __expf(-B0) + __expf(-B1);
        }
#pragma unroll
        for (int r = 0; r < 4; r++) {
          accA[n][r] = 0.f;
          accB[n][r] = 0.f;
        }
      }
    }
  }

  // quad-reduce (lanes sharing a fragment row) and write partials
#pragma unroll
  for (int o = 1; o <= 2; o <<= 1) {
    la0 += __shfl_xor_sync(0xffffffffu, la0, o);
    la1 += __shfl_xor_sync(0xffffffffu, la1, o);
    s0 += __shfl_xor_sync(0xffffffffu, s0, o);
    s1 += __shfl_xor_sync(0xffffffffu, s1, o);
    lb0 += __shfl_xor_sync(0xffffffffu, lb0, o);
    lb1 += __shfl_xor_sync(0xffffffffu, lb1, o);
  }
  if ((lane & 3) == 0) {
    const int r0 = i0 + wm * 16 + (lane >> 2);
    const int slot = (split * 2 + wn) * 3;
    g_part[r0 * 12 + slot + 0] = la0;
    g_part[r0 * 12 + slot + 1] = s0;
    g_part[r0 * 12 + slot + 2] = lb0;
    g_part[(r0 + 8) * 12 + slot + 0] = la1;
    g_part[(r0 + 8) * 12 + slot + 1] = s1;
    g_part[(r0 + 8) * 12 + slot + 2] = lb1;
  }
}

// ---------------- 3) merge partials + deterministic mean ----------------
__global__ void merge_reduce_kernel(float *__restrict__ out) {
  __shared__ float red[256];
  const int tid = threadIdx.x;
  float local = 0.f;
  for (int row = tid; row < NROW; row += 256) {
    const float *p = &g_part[row * 12];
    float L = 0.f, S = 0.f, Lb = 0.f;
#pragma unroll
    for (int k = 0; k < 4; k++) {
      L += p[k * 3 + 0];
      S += p[k * 3 + 1];
      Lb += p[k * 3 + 2];
    }
    // kl_i = sum t*(a-b) - lse(a) + lse(b), fixed shift 0
    local += S / L - logf(L) + logf(Lb);
  }
  red[tid] = local;
  __syncthreads();
#pragma unroll
  for (int o = 128; o > 0; o >>= 1) {
    if (tid < o) red[tid] += red[tid + o];
    __syncthreads();
  }
  if (tid == 0) out[0] = red[0] / (float)NROW;
}

// ---------------- launch ----------------
extern "C" void kernel_launch(void *const *d_in, const int *in_sizes, int n_in,
                              void *d_out, int out_size) {
  const float *X = (const float *)d_in[0];  // cosine_distance_latent (target)
  const float *Y = (const float *)d_in[1];  // mse_latent (predicted)
  float *out = (float *)d_out;

  cudaFuncSetAttribute(gram_kl_kernel,
                       cudaFuncAttributeMaxDynamicSharedMemorySize, SMEM_TOTAL);

  normalize_kernel<<<dim3(NROW, 2), 128>>>(X, Y);
  gram_kl_kernel<<<dim3(NROW / BM, NSPLIT), 256, SMEM_TOTAL>>>();
  merge_reduce_kernel<<<1, 256>>>(out);
}